// round 1
// baseline (speedup 1.0000x reference)
#include <cuda_runtime.h>
#include <math.h>

#define TRACT_N   44
#define SIM_STEPS 20
#define NSTEPS    (TRACT_N + SIM_STEPS)   // 64
#define B_        4
#define L_        16384
#define TILE      128
#define SW        (TILE + 64)             // smem row width (tid+i <= 127+63 = 190 < 192)

// scratch: [21][B][L] tap values (tr[43] after step 43+s), s = 0..20
__device__ float g_scratch[(SIM_STEPS + 1) * B_ * L_];

__global__ __launch_bounds__(TILE)
void tract_sim_kernel(const float* __restrict__ in_audio,
                      const float* __restrict__ refl,
                      const float* __restrict__ fade)
{
    __shared__ float s_r[(TRACT_N + 1) * SW];   // 45 * 192 * 4 = 34.5 KB
    __shared__ float s_F[TRACT_N];

    const int tid = threadIdx.x;
    const int b   = blockIdx.y;
    const int t0  = blockIdx.x * TILE;

    // Stage reflection tile: rows j=0..44, time window [t0, t0+SW), zero-padded past L.
    const float* refl_b = refl + (size_t)b * (TRACT_N + 1) * L_;
    for (int idx = tid; idx < (TRACT_N + 1) * SW; idx += TILE) {
        int j  = idx / SW;
        int tt = t0 + (idx - j * SW);
        s_r[idx] = (tt < L_) ? refl_b[j * L_ + tt] : 0.0f;
    }
    // fade_s = sigmoid(fade), per lane
    if (tid < TRACT_N) {
        float x = fade[tid];
        s_F[tid] = 1.0f / (1.0f + __expf(-x));
    }
    __syncthreads();

    const int t = t0 + tid;

    // Per-column state in registers
    float tr[TRACT_N];
    float tl[TRACT_N];
#pragma unroll
    for (int j = 0; j < TRACT_N; j++) { tr[j] = 0.0f; tl[j] = 0.0f; }
    tr[0] = in_audio[(size_t)b * L_ + t];

    const float* rp = s_r + tid;   // advance by 1 each step

    for (int i = 0; i < NSTEPS; i++) {
        // rnext = r[j+1] for current j; start at r[44]
        float rnext = rp[TRACT_N * SW];
        float carry_tl = 0.0f;     // old tl[j+1]; tl[44] := 0 (shifted_l[43] = 0)
#pragma unroll
        for (int j = TRACT_N - 1; j >= 0; j--) {
            float rj     = rp[j * SW];
            float Fj     = s_F[j];
            float old_tl = tl[j];
            float old_tr = tr[j];
            // new_l[j] = (sl + (sl + tr[j]) * r[j+1]) * F[j],  sl = old tl[j+1]
            float sl = carry_tl;
            float nl = (sl + (sl + old_tr) * rnext) * Fj;
            // new_r[j] = (sr - (sr + tl[j]) * r[j]) * F[j],    sr = old tr[j-1]
            float sr = (j > 0) ? tr[j - 1] : 0.0f;   // descending: tr[j-1] still old
            float nr = (sr - (sr + old_tl) * rj) * Fj;
            tl[j] = nl;
            tr[j] = nr;
            carry_tl = old_tl;
            rnext = rj;
        }
        if (i >= TRACT_N - 1) {
            int s = i - (TRACT_N - 1);               // 0..20
            g_scratch[(size_t)s * (B_ * L_) + (size_t)b * L_ + t] = tr[TRACT_N - 1];
        }
        rp += 1;
    }
}

__global__ __launch_bounds__(256)
void tract_combine_kernel(float* __restrict__ out)
{
    int idx = blockIdx.x * blockDim.x + threadIdx.x;
    if (idx >= B_ * L_) return;
    int t = idx & (L_ - 1);

    float sum = g_scratch[idx];   // s = 0 tap at (b, t)
#pragma unroll
    for (int r = 0; r < SIM_STEPS; r++) {
        if (t >= r + 1)
            sum += g_scratch[(size_t)(r + 1) * (B_ * L_) + idx - (r + 1)];
    }
    out[idx] = sum;
}

extern "C" void kernel_launch(void* const* d_in, const int* in_sizes, int n_in,
                              void* d_out, int out_size)
{
    const float* in_audio = (const float*)d_in[0];   // (4, 1, 16384)
    const float* refl     = (const float*)d_in[1];   // (4, 45, 16384)
    const float* fade     = (const float*)d_in[2];   // (1, 1, 44)
    float* out = (float*)d_out;                      // (4, 1, 16384)

    dim3 g1(L_ / TILE, B_);
    tract_sim_kernel<<<g1, TILE>>>(in_audio, refl, fade);
    tract_combine_kernel<<<(B_ * L_ + 255) / 256, 256>>>(out);
}